// round 16
// baseline (speedup 1.0000x reference)
#include <cuda_runtime.h>
#include <math.h>

#define D       2048
#define NROWS   65536
#define NDREAMS 4
#define KMEM    8
#define MCAND   12

#define MV_BLOCKS 128            // Wq: [0,64), Wg1: [64,128); 64 rows per block
#define SIMS_BLOCKS 1024
#define WC_BLOCKS 256            // 256 blocks x 8 warps = 2048 full rows
// k1 grid layout: [MV][dreams][sims][Wc][gate]
#define K1_WC_BASE  (MV_BLOCKS + NDREAMS + SIMS_BLOCKS)       // 1156
#define K1_SC_BLOCK (K1_WC_BASE + WC_BLOCKS)                  // 1412 gate scalar
#define K1_GRID     (K1_SC_BLOCK + 1)                         // 1413

#define WM_BLOCKS 512            // 512 blocks x 4 rows
#define K23_GRID (1 + WM_BLOCKS) // block 0 = select/logits/softmax

// ---------------- scratch (zero-initialized at module load; reset each launch) ----
__device__ float g_qv_pre[D];        // reset by K23 out-block
__device__ float g_gate_pre[D];      // reset by K23 out-block
__device__ float g_spre[D];          // reset by K23 out-block
__device__ float g_v[D];             // fully overwritten each launch (no atomics)
__device__ float g_C[MCAND * D];     // fully overwritten each launch
__device__ float g_attn[MCAND];      // fully overwritten each launch
__device__ float g_gate;             // overwritten each launch
__device__ float g_pool_v[SIMS_BLOCKS * KMEM];
__device__ int   g_pool_i[SIMS_BLOCKS * KMEM];
__device__ int   cnt_wq, cnt_g1;     // reset by K23 out-block
__device__ int   cnt_af, cnt_w;      // attn flag / Wm completion; reset by out-block

__device__ __forceinline__ float warp_sum(float v) {
#pragma unroll
    for (int off = 16; off; off >>= 1) v += __shfl_down_sync(0xFFFFFFFFu, v, off);
    return v;
}

__device__ __forceinline__ void poll_cnt(volatile int* c, int target, int t) {
    if (t == 0) { while (*c < target) __nanosleep(32); }
    __syncthreads();
    __threadfence();
}

// ======================= K1: bulk (R11 proven version, unchanged) =============
__global__ __launch_bounds__(256, 4) void k1_bulk(const float* __restrict__ z,
                                                  const float* __restrict__ h,
                                                  const float* __restrict__ mem,
                                                  const float* __restrict__ Wq,
                                                  const float* __restrict__ Wg1,
                                                  const float* __restrict__ Wc,
                                                  const float* __restrict__ noise,
                                                  const float* __restrict__ bq,
                                                  const float* __restrict__ ws,
                                                  const float* __restrict__ bg1,
                                                  const float* __restrict__ wg2,
                                                  const float* __restrict__ bg2) {
    __shared__ float zsh[D];
    __shared__ float sscore[64];
    int b = blockIdx.x, t = threadIdx.x;
    int warp = t >> 5, lane = t & 31;

    if (b < MV_BLOCKS) {
        const float* W   = (b < 64) ? Wq : Wg1;
        float*       dst = (b < 64) ? g_qv_pre : g_gate_pre;
        int rb = (b & 63) * 64;
        float acc[8];
#pragma unroll
        for (int k = 0; k < 8; ++k) acc[k] = 0.f;
        for (int i = 0; i < 64; ++i) {
            int row = rb + i;
            float x = (row < D) ? z[row] : h[row - D];
            const float* wr = W + (size_t)row * D;
#pragma unroll
            for (int k = 0; k < 8; ++k) acc[k] += x * wr[t + 256 * k];
        }
#pragma unroll
        for (int k = 0; k < 8; ++k) atomicAdd(&dst[t + 256 * k], acc[k]);
        __threadfence();
        __syncthreads();
        if (t == 0) atomicAdd((b < 64) ? &cnt_wq : &cnt_g1, 1);
    } else if (b < MV_BLOCKS + NDREAMS) {
        __shared__ float red[8];
        int dm = b - MV_BLOCKS;
        float ss = 0.f;
#pragma unroll
        for (int k = 0; k < 8; ++k) {
            int j = t + 256 * k;
            float v = 0.7f * noise[dm * D + j] + 0.3f * z[j];
            zsh[j] = v;
            ss += v * v;
        }
        ss = warp_sum(ss);
        if (lane == 0) red[warp] = ss;
        __syncthreads();
        if (t == 0) {
            float s = 0.f;
#pragma unroll
            for (int w = 0; w < 8; ++w) s += red[w];
            red[0] = s;
        }
        __syncthreads();
        float inv = 1.0f / fmaxf(sqrtf(red[0]), 1e-12f);
#pragma unroll
        for (int k = 0; k < 8; ++k) {
            int j = t + 256 * k;
            g_C[(KMEM + dm) * D + j] = zsh[j] * inv;
        }
    } else if (b < K1_WC_BASE) {
        int sb = b - MV_BLOCKS - NDREAMS;            // 0..1023
#pragma unroll
        for (int k = 0; k < 8; ++k) zsh[t + 256 * k] = z[t + 256 * k];
        __syncthreads();
        const float4* z4 = (const float4*)zsh;
        int wg = sb * 8 + warp;                      // 0..8191
#pragma unroll 1
        for (int p = 0; p < 4; ++p) {
            int rA = 2 * wg + 16384 * p;
            const float4* A4 = (const float4*)(mem + (size_t)rA * D);
            const float4* B4 = (const float4*)(mem + (size_t)(rA + 1) * D);
            float dA0 = 0, dA1 = 0, nA0 = 0, nA1 = 0;
            float dB0 = 0, dB1 = 0, nB0 = 0, nB1 = 0;
#pragma unroll
            for (int it = 0; it < 16; ++it) {
                float4 va = __ldcs(&A4[lane + 32 * it]);
                float4 vb = __ldcs(&B4[lane + 32 * it]);
                float4 zz = z4[lane + 32 * it];
                dA0 += va.x * zz.x + va.y * zz.y;
                dA1 += va.z * zz.z + va.w * zz.w;
                nA0 += va.x * va.x + va.y * va.y;
                nA1 += va.z * va.z + va.w * va.w;
                dB0 += vb.x * zz.x + vb.y * zz.y;
                dB1 += vb.z * zz.z + vb.w * zz.w;
                nB0 += vb.x * vb.x + vb.y * vb.y;
                nB1 += vb.z * vb.z + vb.w * vb.w;
            }
            float dA = warp_sum(dA0 + dA1);
            float nA = warp_sum(nA0 + nA1);
            float dB = warp_sum(dB0 + dB1);
            float nB = warp_sum(nB0 + nB1);
            if (lane == 0) {
                sscore[warp * 8 + p * 2]     = dA * rsqrtf(nA);
                sscore[warp * 8 + p * 2 + 1] = dB * rsqrtf(nB);
            }
        }
        __syncthreads();

        if (warp == 0) {
            int s0 = lane, s1 = lane + 32;
            float v0 = sscore[s0], v1 = sscore[s1];
            int r0 = 2 * (sb * 8 + (s0 >> 3)) + 16384 * ((s0 & 7) >> 1) + (s0 & 1);
            int r1 = 2 * (sb * 8 + (s1 >> 3)) + 16384 * ((s1 & 7) >> 1) + (s1 & 1);
            if (v1 > v0) { float tv = v0; v0 = v1; v1 = tv; int ti = r0; r0 = r1; r1 = ti; }
#pragma unroll 1
            for (int p = 0; p < KMEM; ++p) {
                float best = v0; int bl = lane;
#pragma unroll
                for (int off = 16; off; off >>= 1) {
                    float ov = __shfl_down_sync(0xFFFFFFFFu, best, off);
                    int obl  = __shfl_down_sync(0xFFFFFFFFu, bl, off);
                    if (ov > best) { best = ov; bl = obl; }
                }
                int wl = __shfl_sync(0xFFFFFFFFu, bl, 0);
                float wv = __shfl_sync(0xFFFFFFFFu, v0, wl);
                int  wr = __shfl_sync(0xFFFFFFFFu, r0, wl);
                if (lane == 0) { g_pool_v[sb * 8 + p] = wv; g_pool_i[sb * 8 + p] = wr; }
                if (lane == wl) { v0 = v1; r0 = r1; v1 = -INFINITY; }
            }
        }
    } else if (b < K1_SC_BLOCK) {
        // ---- Wc full-row matvec (tail wave; Wq long done -> poll instant) ----
        int wb = b - K1_WC_BASE;                     // 0..255
        poll_cnt(&cnt_wq, 64, t);
#pragma unroll
        for (int k = 0; k < 8; ++k) {
            int j = t + 256 * k;
            zsh[j] = tanhf(__ldcg(&g_qv_pre[j]) + bq[j]) * ws[j];
        }
        __syncthreads();
        int row = wb * 8 + warp;                     // 0..2047
        const float4* wr = (const float4*)(Wc + (size_t)row * D);
        const float4* q4 = (const float4*)zsh;
        float a0 = 0, a1 = 0, a2 = 0, a3 = 0;
#pragma unroll
        for (int it = 0; it < 16; ++it) {
            float4 wv = __ldcs(&wr[lane + 32 * it]);
            float4 qv = q4[lane + 32 * it];
            a0 += wv.x * qv.x; a1 += wv.y * qv.y; a2 += wv.z * qv.z; a3 += wv.w * qv.w;
        }
        float s = warp_sum((a0 + a1) + (a2 + a3));
        if (lane == 0) g_v[row] = s;
    } else {
        // ---- gate scalar (cb dropped: softmax is shift-invariant) ----
        __shared__ float sgp[8];
        poll_cnt(&cnt_g1, 64, t);
        float gp = 0.f;
#pragma unroll
        for (int k = 0; k < 8; ++k) {
            int j = t + 256 * k;
            gp += tanhf(__ldcg(&g_gate_pre[j]) + bg1[j]) * wg2[j];
        }
        gp = warp_sum(gp);
        if (lane == 0) sgp[warp] = gp;
        __syncthreads();
        if (t == 0) {
            float g = 0.f;
#pragma unroll
            for (int w2 = 0; w2 < 8; ++w2) g += sgp[w2];
            g_gate = 1.0f / (1.0f + expf(-(g + bg2[0])));
        }
    }
}

// ======================= K23: select (block 0) -> flag -> Wm blocks ===========
// b==0   : top-8 from pool -> gather protos -> logits -> softmax -> flag
// b>=1   : GENTLE spin (2us nanosleep -> no L2-slice hammering), then load Wm
//          rows (float4), FMA, smem transpose, coalesced atomics;
//          last block -> output + reset all state for graph replay.
__global__ __launch_bounds__(256) void k23_fin(const float* __restrict__ mem,
                                               const float* __restrict__ Wm,
                                               const float* __restrict__ bm,
                                               float* __restrict__ out) {
    int b = blockIdx.x, t = threadIdx.x;
    int warp = t >> 5, lane = t & 31;

    if (b == 0) {
        __shared__ float pv2[64];
        __shared__ int   pi2[64];
        __shared__ int   sidx[KMEM];
        __shared__ float slog[MCAND];
        float bv[KMEM]; int bi[KMEM];
#pragma unroll
        for (int q = 0; q < KMEM; ++q) { bv[q] = -INFINITY; bi[q] = 0; }
#pragma unroll 1
        for (int f = 0; f < 32; ++f) {
            int e = t + 256 * f;
            float s = g_pool_v[e];
            if (s > bv[KMEM - 1]) {
                bv[KMEM - 1] = s; bi[KMEM - 1] = g_pool_i[e];
#pragma unroll
                for (int q = KMEM - 1; q > 0; --q) {
                    if (bv[q] > bv[q - 1]) {
                        float tv = bv[q - 1]; int ti = bi[q - 1];
                        bv[q - 1] = bv[q]; bi[q - 1] = bi[q];
                        bv[q] = tv; bi[q] = ti;
                    }
                }
            }
        }
#pragma unroll 1
        for (int p = 0; p < KMEM; ++p) {
            float v = bv[0]; int id = bi[0]; int ln = lane;
#pragma unroll
            for (int off = 16; off; off >>= 1) {
                float ov = __shfl_down_sync(0xFFFFFFFFu, v, off);
                int oid  = __shfl_down_sync(0xFFFFFFFFu, id, off);
                int oln  = __shfl_down_sync(0xFFFFFFFFu, ln, off);
                if (ov > v) { v = ov; id = oid; ln = oln; }
            }
            int wln = __shfl_sync(0xFFFFFFFFu, ln, 0);
            if (lane == 0) { pv2[warp * 8 + p] = v; pi2[warp * 8 + p] = id; }
            if (lane == wln) {
#pragma unroll
                for (int q = 0; q < KMEM - 1; ++q) { bv[q] = bv[q + 1]; bi[q] = bi[q + 1]; }
                bv[KMEM - 1] = -INFINITY;
            }
        }
        __syncthreads();
        if (warp == 0) {
            float v0 = pv2[lane], v1 = pv2[lane + 32];
            int   i0 = pi2[lane], i1 = pi2[lane + 32];
            if (v1 > v0) { float tv = v0; v0 = v1; v1 = tv; int ti = i0; i0 = i1; i1 = ti; }
#pragma unroll 1
            for (int p = 0; p < KMEM; ++p) {
                float best = v0; int bl = lane;
#pragma unroll
                for (int off = 16; off; off >>= 1) {
                    float ov = __shfl_down_sync(0xFFFFFFFFu, best, off);
                    int obl  = __shfl_down_sync(0xFFFFFFFFu, bl, off);
                    if (ov > best) { best = ov; bl = obl; }
                }
                int wl = __shfl_sync(0xFFFFFFFFu, bl, 0);
                int wi = __shfl_sync(0xFFFFFFFFu, i0, wl);
                if (lane == 0) sidx[p] = wi;
                if (lane == wl) { v0 = v1; i0 = i1; v1 = -INFINITY; }
            }
        }
        __syncthreads();
        // gather 8 protos (4096 float4) with 256 threads
#pragma unroll 1
        for (int idx = t; idx < KMEM * (D / 4); idx += 256) {
            int m = idx >> 9, off = idx & 511;
            ((float4*)(g_C + m * D))[off] =
                ((const float4*)(mem + (size_t)sidx[m] * D))[off];
        }
        __syncthreads();
        // logits: warp w -> m = w, w+8 (float4)
#pragma unroll 1
        for (int m = warp; m < MCAND; m += 8) {
            const float4* c4 = (const float4*)(g_C + m * D);
            const float4* v4 = (const float4*)g_v;
            float a0 = 0, a1 = 0;
#pragma unroll
            for (int it = 0; it < 16; ++it) {
                float4 c = c4[lane + 32 * it];
                float4 v = v4[lane + 32 * it];
                a0 += c.x * v.x + c.y * v.y;
                a1 += c.z * v.z + c.w * v.w;
            }
            float a = warp_sum(a0 + a1);
            if (lane == 0) slog[m] = a;
        }
        __syncthreads();
        if (t == 0) {
            float lg[MCAND]; float mx = -INFINITY;
#pragma unroll
            for (int m = 0; m < MCAND; ++m) {
                lg[m] = slog[m];
                mx = fmaxf(mx, lg[m]);
            }
            float den = 0.f;
#pragma unroll
            for (int m = 0; m < MCAND; ++m) { lg[m] = expf(lg[m] - mx); den += lg[m]; }
            float inv = 1.0f / den;
#pragma unroll
            for (int m = 0; m < MCAND; ++m) g_attn[m] = lg[m] * inv;
            __threadfence();
            atomicExch(&cnt_af, 1);
        }
    } else {
        __shared__ float sattn[MCAND];
        __shared__ float sx[4];
        __shared__ float sacc[D];
        __shared__ int   smlast;
        int rb = (b - 1) * 4;

        // ---- GENTLE spin: 2us sleep between polls -> ~250M req/s chip-wide,
        //      no L2-slice saturation, block 0 runs on a quiet chip ----
        if (t == 0) {
            volatile int* c = &cnt_af;
            while (*c < 1) __nanosleep(2048);
        }
        __syncthreads();
        __threadfence();
        if (t < MCAND) sattn[t] = __ldcg(&g_attn[t]);
        __syncthreads();
        if (t < 4) {
            float x = 0.f;
#pragma unroll
            for (int m = 0; m < MCAND; ++m) x += sattn[m] * __ldcg(&g_C[m * D + rb + t]);
            sx[t] = x;
        }
        __syncthreads();

        float4 a0 = make_float4(0.f, 0.f, 0.f, 0.f);
        float4 a1 = make_float4(0.f, 0.f, 0.f, 0.f);
#pragma unroll
        for (int i = 0; i < 4; ++i) {
            float x = sx[i];
            const float4* wr = (const float4*)(Wm + (size_t)(rb + i) * D);
            float4 w0 = __ldcs(&wr[t]);
            float4 w1 = __ldcs(&wr[t + 256]);
            a0.x += x * w0.x; a0.y += x * w0.y; a0.z += x * w0.z; a0.w += x * w0.w;
            a1.x += x * w1.x; a1.y += x * w1.y; a1.z += x * w1.z; a1.w += x * w1.w;
        }
        // transpose via smem so global atomics stay coalesced scalar form
        ((float4*)sacc)[t]       = a0;
        ((float4*)sacc)[t + 256] = a1;
        __syncthreads();
#pragma unroll
        for (int k = 0; k < 8; ++k) atomicAdd(&g_spre[t + 256 * k], sacc[t + 256 * k]);
        __threadfence();
        __syncthreads();
        if (t == 0) smlast = atomicAdd(&cnt_w, 1);
        __syncthreads();
        if (smlast == WM_BLOCKS - 1) {
            __threadfence();
            float g = g_gate;
#pragma unroll
            for (int k = 0; k < 8; ++k) {
                int j = t + 256 * k;
                out[j] = g * tanhf(__ldcg(&g_spre[j]) + bm[j]);
                g_spre[j] = 0.f;
                g_qv_pre[j] = 0.f;
                g_gate_pre[j] = 0.f;
            }
            if (t == 0) {
                atomicExch(&cnt_w, 0);
                atomicExch(&cnt_af, 0);
                atomicExch(&cnt_wq, 0);
                atomicExch(&cnt_g1, 0);
            }
        }
    }
}

// ======================= launch =======================
extern "C" void kernel_launch(void* const* d_in, const int* in_sizes, int n_in,
                              void* d_out, int out_size) {
    const float* z     = (const float*)d_in[0];
    const float* h     = (const float*)d_in[1];
    const float* mem   = (const float*)d_in[2];
    const float* noise = (const float*)d_in[3];
    const float* Wq    = (const float*)d_in[4];
    const float* bq    = (const float*)d_in[5];
    const float* Wc    = (const float*)d_in[6];
    const float* ws    = (const float*)d_in[8];
    const float* Wm    = (const float*)d_in[10];
    const float* bm    = (const float*)d_in[11];
    const float* Wg1   = (const float*)d_in[12];
    const float* bg1   = (const float*)d_in[13];
    const float* wg2   = (const float*)d_in[14];
    const float* bg2   = (const float*)d_in[15];
    float* out = (float*)d_out;

    k1_bulk<<<K1_GRID, 256>>>(z, h, mem, Wq, Wg1, Wc, noise,
                              bq, ws, bg1, wg2, bg2);
    k23_fin<<<K23_GRID, 256>>>(mem, Wm, bm, out);
}

// round 17
// speedup vs baseline: 1.2021x; 1.2021x over previous
#include <cuda_runtime.h>
#include <math.h>

#define D       2048
#define NROWS   65536
#define NDREAMS 4
#define KMEM    8
#define MCAND   12

#define MV_BLOCKS 128            // Wq: [0,64), Wg1: [64,128); 64 rows per block
#define SIMS_BLOCKS 1024
#define WC_BLOCKS 256            // 256 blocks x 8 warps = 2048 full rows
// k1 grid layout: [MV][dreams][sims][Wc][gate]
#define K1_WC_BASE  (MV_BLOCKS + NDREAMS + SIMS_BLOCKS)       // 1156
#define K1_SC_BLOCK (K1_WC_BASE + WC_BLOCKS)                  // 1412 gate scalar
#define K1_GRID     (K1_SC_BLOCK + 1)                         // 1413

#define WM_RG 128                // row-groups (16 rows each)
#define WM_CG 4                  // column-groups (512 cols each)
#define WM_BLOCKS (WM_RG * WM_CG)    // 512
#define K3_GRID WM_BLOCKS

// ---------------- scratch (zero-initialized at module load; reset each launch) ----
__device__ float g_qv_pre[D];        // reset by K3 out-block
__device__ float g_gate_pre[D];      // reset by K3 out-block
__device__ float g_spre[D];          // reset by K3 out-block
__device__ float g_v[D];             // fully overwritten each launch (no atomics)
__device__ float g_C[MCAND * D];     // fully overwritten each launch
__device__ float g_attn[MCAND];      // fully overwritten each launch
__device__ float g_gate;             // overwritten each launch
__device__ float g_pool_v[SIMS_BLOCKS * KMEM];
__device__ int   g_pool_i[SIMS_BLOCKS * KMEM];
__device__ int   cnt_wq, cnt_g1, cnt_w;   // reset by K3 out-block

__device__ __forceinline__ float warp_sum(float v) {
#pragma unroll
    for (int off = 16; off; off >>= 1) v += __shfl_down_sync(0xFFFFFFFFu, v, off);
    return v;
}

__device__ __forceinline__ void poll_cnt(volatile int* c, int target, int t) {
    if (t == 0) { while (*c < target) __nanosleep(32); }
    __syncthreads();
    __threadfence();
}

// ======================= K1: bulk (R11 proven version, unchanged) =============
__global__ __launch_bounds__(256, 4) void k1_bulk(const float* __restrict__ z,
                                                  const float* __restrict__ h,
                                                  const float* __restrict__ mem,
                                                  const float* __restrict__ Wq,
                                                  const float* __restrict__ Wg1,
                                                  const float* __restrict__ Wc,
                                                  const float* __restrict__ noise,
                                                  const float* __restrict__ bq,
                                                  const float* __restrict__ ws,
                                                  const float* __restrict__ bg1,
                                                  const float* __restrict__ wg2,
                                                  const float* __restrict__ bg2) {
    __shared__ float zsh[D];
    __shared__ float sscore[64];
    int b = blockIdx.x, t = threadIdx.x;
    int warp = t >> 5, lane = t & 31;

    if (b < MV_BLOCKS) {
        const float* W   = (b < 64) ? Wq : Wg1;
        float*       dst = (b < 64) ? g_qv_pre : g_gate_pre;
        int rb = (b & 63) * 64;
        float acc[8];
#pragma unroll
        for (int k = 0; k < 8; ++k) acc[k] = 0.f;
        for (int i = 0; i < 64; ++i) {
            int row = rb + i;
            float x = (row < D) ? z[row] : h[row - D];
            const float* wr = W + (size_t)row * D;
#pragma unroll
            for (int k = 0; k < 8; ++k) acc[k] += x * wr[t + 256 * k];
        }
#pragma unroll
        for (int k = 0; k < 8; ++k) atomicAdd(&dst[t + 256 * k], acc[k]);
        __threadfence();
        __syncthreads();
        if (t == 0) atomicAdd((b < 64) ? &cnt_wq : &cnt_g1, 1);
    } else if (b < MV_BLOCKS + NDREAMS) {
        __shared__ float red[8];
        int dm = b - MV_BLOCKS;
        float ss = 0.f;
#pragma unroll
        for (int k = 0; k < 8; ++k) {
            int j = t + 256 * k;
            float v = 0.7f * noise[dm * D + j] + 0.3f * z[j];
            zsh[j] = v;
            ss += v * v;
        }
        ss = warp_sum(ss);
        if (lane == 0) red[warp] = ss;
        __syncthreads();
        if (t == 0) {
            float s = 0.f;
#pragma unroll
            for (int w = 0; w < 8; ++w) s += red[w];
            red[0] = s;
        }
        __syncthreads();
        float inv = 1.0f / fmaxf(sqrtf(red[0]), 1e-12f);
#pragma unroll
        for (int k = 0; k < 8; ++k) {
            int j = t + 256 * k;
            g_C[(KMEM + dm) * D + j] = zsh[j] * inv;
        }
    } else if (b < K1_WC_BASE) {
        int sb = b - MV_BLOCKS - NDREAMS;            // 0..1023
#pragma unroll
        for (int k = 0; k < 8; ++k) zsh[t + 256 * k] = z[t + 256 * k];
        __syncthreads();
        const float4* z4 = (const float4*)zsh;
        int wg = sb * 8 + warp;                      // 0..8191
#pragma unroll 1
        for (int p = 0; p < 4; ++p) {
            int rA = 2 * wg + 16384 * p;
            const float4* A4 = (const float4*)(mem + (size_t)rA * D);
            const float4* B4 = (const float4*)(mem + (size_t)(rA + 1) * D);
            float dA0 = 0, dA1 = 0, nA0 = 0, nA1 = 0;
            float dB0 = 0, dB1 = 0, nB0 = 0, nB1 = 0;
#pragma unroll
            for (int it = 0; it < 16; ++it) {
                float4 va = __ldcs(&A4[lane + 32 * it]);
                float4 vb = __ldcs(&B4[lane + 32 * it]);
                float4 zz = z4[lane + 32 * it];
                dA0 += va.x * zz.x + va.y * zz.y;
                dA1 += va.z * zz.z + va.w * zz.w;
                nA0 += va.x * va.x + va.y * va.y;
                nA1 += va.z * va.z + va.w * va.w;
                dB0 += vb.x * zz.x + vb.y * zz.y;
                dB1 += vb.z * zz.z + vb.w * zz.w;
                nB0 += vb.x * vb.x + vb.y * vb.y;
                nB1 += vb.z * vb.z + vb.w * vb.w;
            }
            float dA = warp_sum(dA0 + dA1);
            float nA = warp_sum(nA0 + nA1);
            float dB = warp_sum(dB0 + dB1);
            float nB = warp_sum(nB0 + nB1);
            if (lane == 0) {
                sscore[warp * 8 + p * 2]     = dA * rsqrtf(nA);
                sscore[warp * 8 + p * 2 + 1] = dB * rsqrtf(nB);
            }
        }
        __syncthreads();

        if (warp == 0) {
            int s0 = lane, s1 = lane + 32;
            float v0 = sscore[s0], v1 = sscore[s1];
            int r0 = 2 * (sb * 8 + (s0 >> 3)) + 16384 * ((s0 & 7) >> 1) + (s0 & 1);
            int r1 = 2 * (sb * 8 + (s1 >> 3)) + 16384 * ((s1 & 7) >> 1) + (s1 & 1);
            if (v1 > v0) { float tv = v0; v0 = v1; v1 = tv; int ti = r0; r0 = r1; r1 = ti; }
#pragma unroll 1
            for (int p = 0; p < KMEM; ++p) {
                float best = v0; int bl = lane;
#pragma unroll
                for (int off = 16; off; off >>= 1) {
                    float ov = __shfl_down_sync(0xFFFFFFFFu, best, off);
                    int obl  = __shfl_down_sync(0xFFFFFFFFu, bl, off);
                    if (ov > best) { best = ov; bl = obl; }
                }
                int wl = __shfl_sync(0xFFFFFFFFu, bl, 0);
                float wv = __shfl_sync(0xFFFFFFFFu, v0, wl);
                int  wr = __shfl_sync(0xFFFFFFFFu, r0, wl);
                if (lane == 0) { g_pool_v[sb * 8 + p] = wv; g_pool_i[sb * 8 + p] = wr; }
                if (lane == wl) { v0 = v1; r0 = r1; v1 = -INFINITY; }
            }
        }
    } else if (b < K1_SC_BLOCK) {
        // ---- Wc full-row matvec (tail wave; Wq long done -> poll instant) ----
        int wb = b - K1_WC_BASE;                     // 0..255
        poll_cnt(&cnt_wq, 64, t);
#pragma unroll
        for (int k = 0; k < 8; ++k) {
            int j = t + 256 * k;
            zsh[j] = tanhf(__ldcg(&g_qv_pre[j]) + bq[j]) * ws[j];
        }
        __syncthreads();
        int row = wb * 8 + warp;                     // 0..2047
        const float4* wr = (const float4*)(Wc + (size_t)row * D);
        const float4* q4 = (const float4*)zsh;
        float a0 = 0, a1 = 0, a2 = 0, a3 = 0;
#pragma unroll
        for (int it = 0; it < 16; ++it) {
            float4 wv = __ldcs(&wr[lane + 32 * it]);
            float4 qv = q4[lane + 32 * it];
            a0 += wv.x * qv.x; a1 += wv.y * qv.y; a2 += wv.z * qv.z; a3 += wv.w * qv.w;
        }
        float s = warp_sum((a0 + a1) + (a2 + a3));
        if (lane == 0) g_v[row] = s;
    } else {
        // ---- gate scalar (cb dropped: softmax is shift-invariant) ----
        __shared__ float sgp[8];
        poll_cnt(&cnt_g1, 64, t);
        float gp = 0.f;
#pragma unroll
        for (int k = 0; k < 8; ++k) {
            int j = t + 256 * k;
            gp += tanhf(__ldcg(&g_gate_pre[j]) + bg1[j]) * wg2[j];
        }
        gp = warp_sum(gp);
        if (lane == 0) sgp[warp] = gp;
        __syncthreads();
        if (t == 0) {
            float g = 0.f;
#pragma unroll
            for (int w2 = 0; w2 < 8; ++w2) g += sgp[w2];
            g_gate = 1.0f / (1.0f + expf(-(g + bg2[0])));
        }
    }
}

// ======================= K2: select + gather + logits + softmax (1 block) =====
__global__ __launch_bounds__(1024) void k2_sel(const float* __restrict__ mem) {
    __shared__ float pv2[256];
    __shared__ int   pi2[256];
    __shared__ int   sidx[KMEM];
    __shared__ float slog[MCAND];
    int t = threadIdx.x, lane = t & 31, warp = t >> 5;

    float bv[KMEM]; int bi[KMEM];
#pragma unroll
    for (int q = 0; q < KMEM; ++q) { bv[q] = -INFINITY; bi[q] = 0; }
#pragma unroll 1
    for (int f = 0; f < 8; ++f) {
        int e = t + 1024 * f;
        float s = g_pool_v[e];
        if (s > bv[KMEM - 1]) {
            bv[KMEM - 1] = s; bi[KMEM - 1] = g_pool_i[e];
#pragma unroll
            for (int q = KMEM - 1; q > 0; --q) {
                if (bv[q] > bv[q - 1]) {
                    float tv = bv[q - 1]; int ti = bi[q - 1];
                    bv[q - 1] = bv[q]; bi[q - 1] = bi[q];
                    bv[q] = tv; bi[q] = ti;
                }
            }
        }
    }
#pragma unroll 1
    for (int p = 0; p < KMEM; ++p) {
        float v = bv[0]; int id = bi[0]; int ln = lane;
#pragma unroll
        for (int off = 16; off; off >>= 1) {
            float ov = __shfl_down_sync(0xFFFFFFFFu, v, off);
            int oid  = __shfl_down_sync(0xFFFFFFFFu, id, off);
            int oln  = __shfl_down_sync(0xFFFFFFFFu, ln, off);
            if (ov > v) { v = ov; id = oid; ln = oln; }
        }
        int wln = __shfl_sync(0xFFFFFFFFu, ln, 0);
        if (lane == 0) { pv2[warp * 8 + p] = v; pi2[warp * 8 + p] = id; }
        if (lane == wln) {
#pragma unroll
            for (int q = 0; q < KMEM - 1; ++q) { bv[q] = bv[q + 1]; bi[q] = bi[q + 1]; }
            bv[KMEM - 1] = -INFINITY;
        }
    }
    __syncthreads();
    if (warp == 0) {
#pragma unroll 1
        for (int p = 0; p < KMEM; ++p) {
            float best = -INFINITY; int bslot = lane;
#pragma unroll
            for (int e = 0; e < 8; ++e) {
                int slot = lane + 32 * e;
                float v = pv2[slot];
                if (v > best) { best = v; bslot = slot; }
            }
#pragma unroll
            for (int off = 16; off; off >>= 1) {
                float ov = __shfl_down_sync(0xFFFFFFFFu, best, off);
                int osl  = __shfl_down_sync(0xFFFFFFFFu, bslot, off);
                if (ov > best) { best = ov; bslot = osl; }
            }
            if (lane == 0) { sidx[p] = pi2[bslot]; pv2[bslot] = -INFINITY; }
            __syncwarp();
        }
    }
    __syncthreads();
    // gather 8 protos (4096 float4) with 1024 threads
#pragma unroll 1
    for (int idx = t; idx < KMEM * (D / 4); idx += 1024) {
        int m = idx >> 9, off = idx & 511;
        ((float4*)(g_C + m * D))[off] =
            ((const float4*)(mem + (size_t)sidx[m] * D))[off];
    }
    __syncthreads();
    // logits: warp m computes dot(C[m], v) with float4
    if (warp < MCAND) {
        const float4* c4 = (const float4*)(g_C + warp * D);
        const float4* v4 = (const float4*)g_v;
        float a0 = 0, a1 = 0;
#pragma unroll
        for (int it = 0; it < 16; ++it) {
            float4 c = c4[lane + 32 * it];
            float4 v = v4[lane + 32 * it];
            a0 += c.x * v.x + c.y * v.y;
            a1 += c.z * v.z + c.w * v.w;
        }
        float a = warp_sum(a0 + a1);
        if (lane == 0) slog[warp] = a;
    }
    __syncthreads();
    if (t == 0) {
        float lg[MCAND]; float mx = -INFINITY;
#pragma unroll
        for (int m = 0; m < MCAND; ++m) {
            lg[m] = slog[m];
            mx = fmaxf(mx, lg[m]);
        }
        float den = 0.f;
#pragma unroll
        for (int m = 0; m < MCAND; ++m) { lg[m] = expf(lg[m] - mx); den += lg[m]; }
        float inv = 1.0f / den;
#pragma unroll
        for (int m = 0; m < MCAND; ++m) g_attn[m] = lg[m] * inv;
    }
}

// ======================= K3: Wm matvec, 2D partition (128 rg x 4 cg) ==========
// block b: rg = b>>2 (rows [16rg,16rg+16)), cg = b&3 (cols [512cg, 512cg+512)).
// Each g_spre address receives only 128 atomics (vs 512) -> 4x less L2-atomic
// serialization; loads stay 128B-coalesced; 512-block load parallelism kept.
__global__ __launch_bounds__(256) void k3_fin(const float* __restrict__ Wm,
                                              const float* __restrict__ bm,
                                              float* __restrict__ out) {
    __shared__ float sattn[MCAND];
    __shared__ float sx[16];
    __shared__ int   smlast;
    int b = blockIdx.x, t = threadIdx.x;
    int rg = b >> 2, cg = b & 3;
    int rbase = rg * 16;
    int cbase = cg * 512;

    if (t < MCAND) sattn[t] = g_attn[t];
    __syncthreads();
    if (t < 16) {
        float x = 0.f;
#pragma unroll
        for (int m = 0; m < MCAND; ++m) x += sattn[m] * g_C[m * D + rbase + t];
        sx[t] = x;
    }
    __syncthreads();

    float acc0 = 0.f, acc1 = 0.f;
#pragma unroll
    for (int i = 0; i < 16; ++i) {
        float x = sx[i];
        const float* wr = Wm + (size_t)(rbase + i) * D + cbase;
        acc0 += x * __ldcs(&wr[t]);
        acc1 += x * __ldcs(&wr[t + 256]);
    }
    atomicAdd(&g_spre[cbase + t], acc0);
    atomicAdd(&g_spre[cbase + t + 256], acc1);
    __threadfence();
    __syncthreads();
    if (t == 0) smlast = atomicAdd(&cnt_w, 1);
    __syncthreads();
    if (smlast == WM_BLOCKS - 1) {
        __threadfence();
        float g = g_gate;
#pragma unroll
        for (int k = 0; k < 8; ++k) {
            int j = t + 256 * k;
            out[j] = g * tanhf(__ldcg(&g_spre[j]) + bm[j]);
            g_spre[j] = 0.f;
            g_qv_pre[j] = 0.f;
            g_gate_pre[j] = 0.f;
        }
        if (t == 0) {
            atomicExch(&cnt_w, 0);
            atomicExch(&cnt_wq, 0);
            atomicExch(&cnt_g1, 0);
        }
    }
}

// ======================= launch =======================
extern "C" void kernel_launch(void* const* d_in, const int* in_sizes, int n_in,
                              void* d_out, int out_size) {
    const float* z     = (const float*)d_in[0];
    const float* h     = (const float*)d_in[1];
    const float* mem   = (const float*)d_in[2];
    const float* noise = (const float*)d_in[3];
    const float* Wq    = (const float*)d_in[4];
    const float* bq    = (const float*)d_in[5];
    const float* Wc    = (const float*)d_in[6];
    const float* ws    = (const float*)d_in[8];
    const float* Wm    = (const float*)d_in[10];
    const float* bm    = (const float*)d_in[11];
    const float* Wg1   = (const float*)d_in[12];
    const float* bg1   = (const float*)d_in[13];
    const float* wg2   = (const float*)d_in[14];
    const float* bg2   = (const float*)d_in[15];
    float* out = (float*)d_out;

    k1_bulk<<<K1_GRID, 256>>>(z, h, mem, Wq, Wg1, Wc, noise,
                              bq, ws, bg1, wg2, bg2);
    k2_sel<<<1, 1024>>>(mem);
    k3_fin<<<K3_GRID, 256>>>(Wm, bm, out);
}